// round 1
// baseline (speedup 1.0000x reference)
#include <cuda_runtime.h>
#include <math.h>

#define SS 2048
#define RR 512
#define DIMD 64
#define NH 8
#define NT 512
#define MSTR 68   // padded row stride for m in smem (conflict-free column walks)
#define HSTR 68   // padded row stride for hidden buffer

// ---- shared memory layout (float offsets) ----
static constexpr int OFF_M    = 0;                  // 512*68 = 34816
static constexpr int OFF_WG   = RR * MSTR;          // 4096
static constexpr int OFF_WO   = OFF_WG + 4096;      // 4096
static constexpr int OFF_K    = OFF_WO + 4096;      // 512*8
static constexpr int OFF_V    = OFF_K + 4096;       // 512*8
static constexpr int OFF_HB   = OFF_K;              // alias: 64*68=4352 fits in K+V region
static constexpr int OFF_WK   = OFF_V + 4096;       // 512
static constexpr int OFF_WV   = OFF_WK + 512;       // 512
static constexpr int OFF_MASK = OFF_WV + 512;       // 512
static constexpr int OFF_PART = OFF_MASK + 512;     // 8*64
static constexpr int OFF_POOL = OFF_PART + 512;     // 64
static constexpr int OFF_QH   = OFF_POOL + 64;      // 64
static constexpr int OFF_OF   = OFF_QH + 64;        // 64
static constexpr int OFF_BG   = OFF_OF + 64;        // 64
static constexpr int OFF_BO   = OFF_BG + 64;        // 64
static constexpr int OFF_MS   = OFF_BO + 64;        // 4 (scalar)
static constexpr int SMEM_FLOATS = OFF_MS + 4;
static constexpr int SMEM_BYTES  = SMEM_FLOATS * 4; // ~214 KB

__global__ void __launch_bounds__(NT, 1) ga_kernel(
    const float* __restrict__ m, const float* __restrict__ mask,
    const float* __restrict__ Wq, const float* __restrict__ Wk,
    const float* __restrict__ Wv, const float* __restrict__ Wg,
    const float* __restrict__ bg, const float* __restrict__ Wo,
    const float* __restrict__ bo, float* __restrict__ out)
{
    extern __shared__ float sm[];
    const int s   = blockIdx.x;
    const int tid = threadIdx.x;
    const float* m_s = m + (size_t)s * (RR * DIMD);

    // ---------- Phase 0: stage m tile + weights into smem ----------
    {
        const float4* m4 = (const float4*)m_s;
        #pragma unroll
        for (int i = tid; i < RR * DIMD / 4; i += NT) {
            float4 v = m4[i];
            int r = i >> 4;            // 16 float4 per 64-wide row
            int c = (i & 15) << 2;
            float* dst = &sm[OFF_M + r * MSTR + c];
            dst[0] = v.x; dst[1] = v.y; dst[2] = v.z; dst[3] = v.w;
        }
        #pragma unroll
        for (int i = tid; i < 1024; i += NT) {
            ((float4*)&sm[OFF_WG])[i] = ((const float4*)Wg)[i];
            ((float4*)&sm[OFF_WO])[i] = ((const float4*)Wo)[i];
        }
        sm[OFF_WK + tid < 0 ? 0 : 0] = sm[0]; // no-op guard against compiler warning (removed logically)
        sm[OFF_WK + tid]   = Wk[tid];
        sm[OFF_WV + tid]   = Wv[tid];
        sm[OFF_MASK + tid] = mask[(size_t)s * RR + tid];
        if (tid < 64) { sm[OFF_BG + tid] = bg[tid]; sm[OFF_BO + tid] = bo[tid]; }
    }
    __syncthreads();

    // ---------- Phase 1: masked mean-pool over residues ----------
    {
        int part = tid >> 6, d = tid & 63;
        float acc = 0.f;
        #pragma unroll 8
        for (int j = 0; j < 64; ++j) {
            int r = part * 64 + j;
            acc += sm[OFF_M + r * MSTR + d] * sm[OFF_MASK + r];
        }
        sm[OFF_PART + part * 64 + d] = acc;
    }
    if (tid < 32) {
        float ms = 0.f;
        #pragma unroll
        for (int j = 0; j < 16; ++j) ms += sm[OFF_MASK + tid + 32 * j];
        #pragma unroll
        for (int o = 16; o; o >>= 1) ms += __shfl_xor_sync(0xFFFFFFFFu, ms, o);
        if (tid == 0) sm[OFF_MS] = ms;
    }
    __syncthreads();
    if (tid < 64) {
        float p = 0.f;
        #pragma unroll
        for (int part = 0; part < 8; ++part) p += sm[OFF_PART + part * 64 + tid];
        sm[OFF_POOL + tid] = p / (sm[OFF_MS] + 1e-10f);
    }
    __syncthreads();

    // ---------- Phase 2: q = (pool @ Wq) * hd^-0.5 ----------
    if (tid < 64) {
        float acc = 0.f;
        #pragma unroll 8
        for (int d = 0; d < 64; ++d) acc += sm[OFF_POOL + d] * Wq[d * 64 + tid];
        sm[OFF_QH + tid] = acc * 0.35355339059327373f; // 8^-0.5
    }
    __syncthreads();

    // ---------- Phase 3: k = m@Wk, v = m@Wv (thread r -> 8+8 outputs) ----------
    {
        const int r = tid;
        float ka[8] = {0,0,0,0,0,0,0,0};
        float va[8] = {0,0,0,0,0,0,0,0};
        #pragma unroll 8
        for (int d = 0; d < 64; ++d) {
            float mv = sm[OFF_M + r * MSTR + d];
            float4 wk0 = *(const float4*)&sm[OFF_WK + d * 8];
            float4 wk1 = *(const float4*)&sm[OFF_WK + d * 8 + 4];
            float4 wv0 = *(const float4*)&sm[OFF_WV + d * 8];
            float4 wv1 = *(const float4*)&sm[OFF_WV + d * 8 + 4];
            ka[0] += mv * wk0.x; ka[1] += mv * wk0.y; ka[2] += mv * wk0.z; ka[3] += mv * wk0.w;
            ka[4] += mv * wk1.x; ka[5] += mv * wk1.y; ka[6] += mv * wk1.z; ka[7] += mv * wk1.w;
            va[0] += mv * wv0.x; va[1] += mv * wv0.y; va[2] += mv * wv0.z; va[3] += mv * wv0.w;
            va[4] += mv * wv1.x; va[5] += mv * wv1.y; va[6] += mv * wv1.z; va[7] += mv * wv1.w;
        }
        #pragma unroll
        for (int c = 0; c < 8; ++c) {
            sm[OFF_K + r * 8 + c] = ka[c];
            sm[OFF_V + r * 8 + c] = va[c];
        }
    }
    __syncthreads();

    // ---------- Phase 4: per-head attention (warp w = head w) ----------
    {
        const int warp = tid >> 5, lane = tid & 31;
        if (warp < NH) {
            const int h = warp;
            float qv[8];
            #pragma unroll
            for (int c = 0; c < 8; ++c) qv[c] = sm[OFF_QH + h * 8 + c];

            float sc[16];
            float mx = -1e30f;
            #pragma unroll
            for (int i = 0; i < 16; ++i) {
                int r = i * 32 + lane;
                const float* kr = &sm[OFF_K + r * 8];
                float a = qv[0]*kr[0] + qv[1]*kr[1] + qv[2]*kr[2] + qv[3]*kr[3]
                        + qv[4]*kr[4] + qv[5]*kr[5] + qv[6]*kr[6] + qv[7]*kr[7];
                a += 1e9f * (sm[OFF_MASK + r] - 1.0f);
                sc[i] = a;
                mx = fmaxf(mx, a);
            }
            #pragma unroll
            for (int o = 16; o; o >>= 1) mx = fmaxf(mx, __shfl_xor_sync(0xFFFFFFFFu, mx, o));

            float sum = 0.f;
            float oa[8] = {0,0,0,0,0,0,0,0};
            #pragma unroll
            for (int i = 0; i < 16; ++i) {
                int r = i * 32 + lane;
                float p = __expf(sc[i] - mx);
                sum += p;
                const float* vr = &sm[OFF_V + r * 8];
                #pragma unroll
                for (int c = 0; c < 8; ++c) oa[c] += p * vr[c];
            }
            #pragma unroll
            for (int o = 16; o; o >>= 1) sum += __shfl_xor_sync(0xFFFFFFFFu, sum, o);
            #pragma unroll
            for (int c = 0; c < 8; ++c) {
                #pragma unroll
                for (int o = 16; o; o >>= 1) oa[c] += __shfl_xor_sync(0xFFFFFFFFu, oa[c], o);
            }
            if (lane == 0) {
                float inv = 1.f / sum;
                #pragma unroll
                for (int c = 0; c < 8; ++c) sm[OFF_OF + h * 8 + c] = oa[c] * inv;
            }
        }
    }
    __syncthreads();

    // ---------- Phase 5: gating + output GEMM (64 rows / iter, 8 outputs / thread) ----------
    {
        const int r_local = tid >> 3;       // 0..63
        const int dq = tid & 7;             // 0..7
        const int dA = dq * 4;              // outputs dA..dA+3
        const int dB = 32 + dq * 4;         // and dB..dB+3 (conflict-free LDS.128 pattern)
        float* outs = out + (size_t)s * (RR * DIMD);

        const float4 bgA = *(const float4*)&sm[OFF_BG + dA];
        const float4 bgB = *(const float4*)&sm[OFF_BG + dB];
        const float4 boA = *(const float4*)&sm[OFF_BO + dA];
        const float4 boB = *(const float4*)&sm[OFF_BO + dB];
        const float4 ofA = *(const float4*)&sm[OFF_OF + dA];
        const float4 ofB = *(const float4*)&sm[OFF_OF + dB];

        for (int it = 0; it < 8; ++it) {
            const int r = it * 64 + r_local;

            // --- gate projection: g = sigmoid(m@Wg + bg); h = g * o ---
            float aA0=0,aA1=0,aA2=0,aA3=0, aB0=0,aB1=0,aB2=0,aB3=0;
            #pragma unroll 8
            for (int d2 = 0; d2 < 64; ++d2) {
                float mv = sm[OFF_M + r * MSTR + d2];
                float4 wa = *(const float4*)&sm[OFF_WG + d2 * 64 + dA];
                float4 wb = *(const float4*)&sm[OFF_WG + d2 * 64 + dB];
                aA0 += mv * wa.x; aA1 += mv * wa.y; aA2 += mv * wa.z; aA3 += mv * wa.w;
                aB0 += mv * wb.x; aB1 += mv * wb.y; aB2 += mv * wb.z; aB3 += mv * wb.w;
            }
            float4 hA, hB;
            hA.x = ofA.x / (1.f + __expf(-(aA0 + bgA.x)));
            hA.y = ofA.y / (1.f + __expf(-(aA1 + bgA.y)));
            hA.z = ofA.z / (1.f + __expf(-(aA2 + bgA.z)));
            hA.w = ofA.w / (1.f + __expf(-(aA3 + bgA.w)));
            hB.x = ofB.x / (1.f + __expf(-(aB0 + bgB.x)));
            hB.y = ofB.y / (1.f + __expf(-(aB1 + bgB.y)));
            hB.z = ofB.z / (1.f + __expf(-(aB2 + bgB.z)));
            hB.w = ofB.w / (1.f + __expf(-(aB3 + bgB.w)));
            *(float4*)&sm[OFF_HB + r_local * HSTR + dA] = hA;
            *(float4*)&sm[OFF_HB + r_local * HSTR + dB] = hB;
            __syncthreads();

            // --- output projection: out = h @ Wo + bo ---
            float oA0=0,oA1=0,oA2=0,oA3=0, oB0=0,oB1=0,oB2=0,oB3=0;
            #pragma unroll 8
            for (int j2 = 0; j2 < 64; ++j2) {
                float hv = sm[OFF_HB + r_local * HSTR + j2];
                float4 wa = *(const float4*)&sm[OFF_WO + j2 * 64 + dA];
                float4 wb = *(const float4*)&sm[OFF_WO + j2 * 64 + dB];
                oA0 += hv * wa.x; oA1 += hv * wa.y; oA2 += hv * wa.z; oA3 += hv * wa.w;
                oB0 += hv * wb.x; oB1 += hv * wb.y; oB2 += hv * wb.z; oB3 += hv * wb.w;
            }
            float4 rA, rB;
            rA.x = oA0 + boA.x; rA.y = oA1 + boA.y; rA.z = oA2 + boA.z; rA.w = oA3 + boA.w;
            rB.x = oB0 + boB.x; rB.y = oB1 + boB.y; rB.z = oB2 + boB.z; rB.w = oB3 + boB.w;
            *(float4*)&outs[r * 64 + dA] = rA;
            *(float4*)&outs[r * 64 + dB] = rB;
            __syncthreads();
        }
    }
}

extern "C" void kernel_launch(void* const* d_in, const int* in_sizes, int n_in,
                              void* d_out, int out_size) {
    (void)in_sizes; (void)n_in; (void)out_size;
    const float* m    = (const float*)d_in[0];
    const float* mask = (const float*)d_in[1];
    const float* Wq   = (const float*)d_in[2];
    const float* Wk   = (const float*)d_in[3];
    const float* Wv   = (const float*)d_in[4];
    const float* Wg   = (const float*)d_in[5];
    const float* bg   = (const float*)d_in[6];
    const float* Wo   = (const float*)d_in[7];
    const float* bo   = (const float*)d_in[8];
    float* out = (float*)d_out;

    cudaFuncSetAttribute(ga_kernel, cudaFuncAttributeMaxDynamicSharedMemorySize, SMEM_BYTES);
    ga_kernel<<<SS, NT, SMEM_BYTES>>>(m, mask, Wq, Wk, Wv, Wg, bg, Wo, bo, out);
}

// round 2
// speedup vs baseline: 2.0159x; 2.0159x over previous
#include <cuda_runtime.h>
#include <math.h>

#define SS 2048
#define RR 512
#define DIMD 64
#define NH 8
#define NT 512
#define MSTR 65   // m row stride: MSTR % 4 == 1 -> rgrp rows hit banks {0,8,16,24}
#define KSTR 9    // K/V row stride (odd -> conflict-free lane-strided reads)

// ---- shared memory layout (float offsets) ----
static constexpr int OFF_M    = 0;                   // 512*65 = 33280
static constexpr int OFF_WG   = RR * MSTR;           // 4096
static constexpr int OFF_WO   = OFF_WG + 4096;       // 4096
static constexpr int OFF_K    = OFF_WO + 4096;       // 512*9 = 4608
static constexpr int OFF_V    = OFF_K + RR * KSTR;   // 4608
static constexpr int OFF_WK   = OFF_V + RR * KSTR;   // 512
static constexpr int OFF_WV   = OFF_WK + 512;        // 512
static constexpr int OFF_MASK = OFF_WV + 512;        // 512
static constexpr int OFF_PART = OFF_MASK + 512;      // 8*64
static constexpr int OFF_POOL = OFF_PART + 512;      // 64
static constexpr int OFF_QH   = OFF_POOL + 64;       // 64
static constexpr int OFF_OF   = OFF_QH + 64;         // 64
static constexpr int OFF_BG   = OFF_OF + 64;         // 64
static constexpr int OFF_BO   = OFF_BG + 64;         // 64
static constexpr int OFF_MS   = OFF_BO + 64;         // 4
static constexpr int SMEM_FLOATS = OFF_MS + 4;
static constexpr int SMEM_BYTES  = SMEM_FLOATS * 4;  // ~213 KB

__global__ void __launch_bounds__(NT, 1) ga_kernel(
    const float* __restrict__ m, const float* __restrict__ mask,
    const float* __restrict__ Wq, const float* __restrict__ Wk,
    const float* __restrict__ Wv, const float* __restrict__ Wg,
    const float* __restrict__ bg, const float* __restrict__ Wo,
    const float* __restrict__ bo, float* __restrict__ out)
{
    extern __shared__ float sm[];
    const int s   = blockIdx.x;
    const int tid = threadIdx.x;
    const float* m_s = m + (size_t)s * (RR * DIMD);

    // ---------- Phase 0: stage m tile + weights into smem ----------
    {
        const float4* m4 = (const float4*)m_s;
        #pragma unroll
        for (int i = tid; i < RR * DIMD / 4; i += NT) {
            float4 v = m4[i];
            int r = i >> 4;            // 16 float4 per 64-wide row
            int c = (i & 15) << 2;
            float* dst = &sm[OFF_M + r * MSTR + c];
            dst[0] = v.x; dst[1] = v.y; dst[2] = v.z; dst[3] = v.w;
        }
        #pragma unroll
        for (int i = tid; i < 1024; i += NT) {
            ((float4*)&sm[OFF_WG])[i] = ((const float4*)Wg)[i];
            ((float4*)&sm[OFF_WO])[i] = ((const float4*)Wo)[i];
        }
        sm[OFF_WK + tid]   = Wk[tid];
        sm[OFF_WV + tid]   = Wv[tid];
        sm[OFF_MASK + tid] = mask[(size_t)s * RR + tid];
        if (tid < 64) { sm[OFF_BG + tid] = bg[tid]; sm[OFF_BO + tid] = bo[tid]; }
    }
    __syncthreads();

    // ---------- Phase 1: masked mean-pool over residues ----------
    {
        int part = tid >> 6, d = tid & 63;
        float acc = 0.f;
        #pragma unroll 8
        for (int j = 0; j < 64; ++j) {
            int r = part * 64 + j;
            acc += sm[OFF_M + r * MSTR + d] * sm[OFF_MASK + r];
        }
        sm[OFF_PART + part * 64 + d] = acc;
    }
    if (tid < 32) {
        float ms = 0.f;
        #pragma unroll
        for (int j = 0; j < 16; ++j) ms += sm[OFF_MASK + tid + 32 * j];
        #pragma unroll
        for (int o = 16; o; o >>= 1) ms += __shfl_xor_sync(0xFFFFFFFFu, ms, o);
        if (tid == 0) sm[OFF_MS] = ms;
    }
    __syncthreads();
    if (tid < 64) {
        float p = 0.f;
        #pragma unroll
        for (int part = 0; part < 8; ++part) p += sm[OFF_PART + part * 64 + tid];
        sm[OFF_POOL + tid] = p / (sm[OFF_MS] + 1e-10f);
    }
    __syncthreads();

    // ---------- Phase 2: q = (pool @ Wq) * hd^-0.5 ----------
    if (tid < 64) {
        float acc = 0.f;
        #pragma unroll 8
        for (int d = 0; d < 64; ++d) acc += sm[OFF_POOL + d] * Wq[d * 64 + tid];
        sm[OFF_QH + tid] = acc * 0.35355339059327373f; // 8^-0.5
    }
    __syncthreads();

    // ---------- Phase 3: k = m@Wk, v = m@Wv (thread r -> 8+8 outputs) ----------
    {
        const int r = tid;
        float ka[8] = {0,0,0,0,0,0,0,0};
        float va[8] = {0,0,0,0,0,0,0,0};
        #pragma unroll 8
        for (int d = 0; d < 64; ++d) {
            float mv = sm[OFF_M + r * MSTR + d];
            float4 wk0 = *(const float4*)&sm[OFF_WK + d * 8];
            float4 wk1 = *(const float4*)&sm[OFF_WK + d * 8 + 4];
            float4 wv0 = *(const float4*)&sm[OFF_WV + d * 8];
            float4 wv1 = *(const float4*)&sm[OFF_WV + d * 8 + 4];
            ka[0] += mv * wk0.x; ka[1] += mv * wk0.y; ka[2] += mv * wk0.z; ka[3] += mv * wk0.w;
            ka[4] += mv * wk1.x; ka[5] += mv * wk1.y; ka[6] += mv * wk1.z; ka[7] += mv * wk1.w;
            va[0] += mv * wv0.x; va[1] += mv * wv0.y; va[2] += mv * wv0.z; va[3] += mv * wv0.w;
            va[4] += mv * wv1.x; va[5] += mv * wv1.y; va[6] += mv * wv1.z; va[7] += mv * wv1.w;
        }
        #pragma unroll
        for (int c = 0; c < 8; ++c) {
            sm[OFF_K + r * KSTR + c] = ka[c];
            sm[OFF_V + r * KSTR + c] = va[c];
        }
    }
    __syncthreads();

    // ---------- Phase 4: per-head attention (warp w = head w) ----------
    {
        const int warp = tid >> 5, lane = tid & 31;
        if (warp < NH) {
            const int h = warp;
            float qv[8];
            #pragma unroll
            for (int c = 0; c < 8; ++c) qv[c] = sm[OFF_QH + h * 8 + c];

            float sc[16];
            float mx = -1e30f;
            #pragma unroll
            for (int i = 0; i < 16; ++i) {
                int r = i * 32 + lane;
                const float* kr = &sm[OFF_K + r * KSTR];
                float a = qv[0]*kr[0] + qv[1]*kr[1] + qv[2]*kr[2] + qv[3]*kr[3]
                        + qv[4]*kr[4] + qv[5]*kr[5] + qv[6]*kr[6] + qv[7]*kr[7];
                a += 1e9f * (sm[OFF_MASK + r] - 1.0f);
                sc[i] = a;
                mx = fmaxf(mx, a);
            }
            #pragma unroll
            for (int o = 16; o; o >>= 1) mx = fmaxf(mx, __shfl_xor_sync(0xFFFFFFFFu, mx, o));

            float sum = 0.f;
            float oa[8] = {0,0,0,0,0,0,0,0};
            #pragma unroll
            for (int i = 0; i < 16; ++i) {
                int r = i * 32 + lane;
                float p = __expf(sc[i] - mx);
                sum += p;
                const float* vr = &sm[OFF_V + r * KSTR];
                #pragma unroll
                for (int c = 0; c < 8; ++c) oa[c] += p * vr[c];
            }
            #pragma unroll
            for (int o = 16; o; o >>= 1) sum += __shfl_xor_sync(0xFFFFFFFFu, sum, o);
            #pragma unroll
            for (int c = 0; c < 8; ++c) {
                #pragma unroll
                for (int o = 16; o; o >>= 1) oa[c] += __shfl_xor_sync(0xFFFFFFFFu, oa[c], o);
            }
            if (lane == 0) {
                float inv = 1.f / sum;
                #pragma unroll
                for (int c = 0; c < 8; ++c) sm[OFF_OF + h * 8 + c] = oa[c] * inv;
            }
        }
    }
    __syncthreads();

    // ---------- Phase 5: gating + output GEMM, 8x8 register tile per thread ----------
    // thread (rgrp, cgrp): rows rgrp*8..+7, cols cgrp*8..+7.  cols of one thread
    // = exactly head `cgrp`.  Each warp owns 32 rows (rgrp 4w..4w+3) entirely,
    // so h can overwrite m in place with only a __syncwarp between the GEMMs.
    {
        const int rgrp = tid >> 3;      // 0..63
        const int cgrp = tid & 7;       // 0..7
        const int r0   = rgrp * 8;
        const int col0 = cgrp * 8;
        float* outs = out + (size_t)s * (RR * DIMD);

        const float4 of0 = *(const float4*)&sm[OFF_OF + col0];
        const float4 of1 = *(const float4*)&sm[OFF_OF + col0 + 4];
        const float4 bg0 = *(const float4*)&sm[OFF_BG + col0];
        const float4 bg1 = *(const float4*)&sm[OFF_BG + col0 + 4];
        const float4 bo0 = *(const float4*)&sm[OFF_BO + col0];
        const float4 bo1 = *(const float4*)&sm[OFF_BO + col0 + 4];

        float acc[8][8];
        #pragma unroll
        for (int j = 0; j < 8; ++j)
            #pragma unroll
            for (int c = 0; c < 8; ++c) acc[j][c] = 0.f;

        // --- gate GEMM: acc[j][c] = sum_d m[r0+j][d] * Wg[d][col0+c] ---
        #pragma unroll 4
        for (int d = 0; d < 64; ++d) {
            const float4 w0 = *(const float4*)&sm[OFF_WG + d * 64 + col0];
            const float4 w1 = *(const float4*)&sm[OFF_WG + d * 64 + col0 + 4];
            float mv[8];
            #pragma unroll
            for (int j = 0; j < 8; ++j) mv[j] = sm[OFF_M + (r0 + j) * MSTR + d];
            #pragma unroll
            for (int j = 0; j < 8; ++j) {
                acc[j][0] += mv[j] * w0.x; acc[j][1] += mv[j] * w0.y;
                acc[j][2] += mv[j] * w0.z; acc[j][3] += mv[j] * w0.w;
                acc[j][4] += mv[j] * w1.x; acc[j][5] += mv[j] * w1.y;
                acc[j][6] += mv[j] * w1.z; acc[j][7] += mv[j] * w1.w;
            }
        }

        // h = sigmoid(acc + bg) * o_f  -> overwrite m rows in place
        #pragma unroll
        for (int j = 0; j < 8; ++j) {
            float* hrow = &sm[OFF_M + (r0 + j) * MSTR + col0];
            hrow[0] = of0.x / (1.f + __expf(-(acc[j][0] + bg0.x)));
            hrow[1] = of0.y / (1.f + __expf(-(acc[j][1] + bg0.y)));
            hrow[2] = of0.z / (1.f + __expf(-(acc[j][2] + bg0.z)));
            hrow[3] = of0.w / (1.f + __expf(-(acc[j][3] + bg0.w)));
            hrow[4] = of1.x / (1.f + __expf(-(acc[j][4] + bg1.x)));
            hrow[5] = of1.y / (1.f + __expf(-(acc[j][5] + bg1.y)));
            hrow[6] = of1.z / (1.f + __expf(-(acc[j][6] + bg1.z)));
            hrow[7] = of1.w / (1.f + __expf(-(acc[j][7] + bg1.w)));
        }
        __syncwarp();

        // --- output GEMM: out[j][c] = sum_d h[r0+j][d] * Wo[d][col0+c] + bo ---
        #pragma unroll
        for (int j = 0; j < 8; ++j)
            #pragma unroll
            for (int c = 0; c < 8; ++c) acc[j][c] = 0.f;

        #pragma unroll 4
        for (int d = 0; d < 64; ++d) {
            const float4 w0 = *(const float4*)&sm[OFF_WO + d * 64 + col0];
            const float4 w1 = *(const float4*)&sm[OFF_WO + d * 64 + col0 + 4];
            float hv[8];
            #pragma unroll
            for (int j = 0; j < 8; ++j) hv[j] = sm[OFF_M + (r0 + j) * MSTR + d];
            #pragma unroll
            for (int j = 0; j < 8; ++j) {
                acc[j][0] += hv[j] * w0.x; acc[j][1] += hv[j] * w0.y;
                acc[j][2] += hv[j] * w0.z; acc[j][3] += hv[j] * w0.w;
                acc[j][4] += hv[j] * w1.x; acc[j][5] += hv[j] * w1.y;
                acc[j][6] += hv[j] * w1.z; acc[j][7] += hv[j] * w1.w;
            }
        }

        #pragma unroll
        for (int j = 0; j < 8; ++j) {
            float4 rA, rB;
            rA.x = acc[j][0] + bo0.x; rA.y = acc[j][1] + bo0.y;
            rA.z = acc[j][2] + bo0.z; rA.w = acc[j][3] + bo0.w;
            rB.x = acc[j][4] + bo1.x; rB.y = acc[j][5] + bo1.y;
            rB.z = acc[j][6] + bo1.z; rB.w = acc[j][7] + bo1.w;
            *(float4*)&outs[(r0 + j) * 64 + col0]     = rA;
            *(float4*)&outs[(r0 + j) * 64 + col0 + 4] = rB;
        }
    }
}

extern "C" void kernel_launch(void* const* d_in, const int* in_sizes, int n_in,
                              void* d_out, int out_size) {
    (void)in_sizes; (void)n_in; (void)out_size;
    const float* m    = (const float*)d_in[0];
    const float* mask = (const float*)d_in[1];
    const float* Wq   = (const float*)d_in[2];
    const float* Wk   = (const float*)d_in[3];
    const float* Wv   = (const float*)d_in[4];
    const float* Wg   = (const float*)d_in[5];
    const float* bg   = (const float*)d_in[6];
    const float* Wo   = (const float*)d_in[7];
    const float* bo   = (const float*)d_in[8];
    float* out = (float*)d_out;

    cudaFuncSetAttribute(ga_kernel, cudaFuncAttributeMaxDynamicSharedMemorySize, SMEM_BYTES);
    ga_kernel<<<SS, NT, SMEM_BYTES>>>(m, mask, Wq, Wk, Wv, Wg, bg, Wo, bo, out);
}

// round 3
// speedup vs baseline: 3.9339x; 1.9514x over previous
#include <cuda_runtime.h>
#include <math.h>
#include <stdint.h>

#define SS 2048
#define RR 512
#define NT 512
#define MSTR 68   // % 32 == 4 -> mma A-frag gather (banks 4q+c) conflict-free
#define KSTR 9

// ---- shared memory layout (float offsets) ----
static constexpr int OFF_M    = 0;                    // 512*68 = 34816
static constexpr int OFF_WGF  = RR * MSTR;            // Wg frags (tf32 bits) 4096
static constexpr int OFF_WOF  = OFF_WGF + 4096;       // Wo frags 4096
static constexpr int OFF_WKF  = OFF_WOF + 4096;       // Wk frags 512
static constexpr int OFF_WVF  = OFF_WKF + 512;        // Wv frags 512
static constexpr int OFF_K    = OFF_WVF + 512;        // 512*9
static constexpr int OFF_V    = OFF_K + RR * KSTR;    // 512*9
static constexpr int OFF_MASK = OFF_V + RR * KSTR;    // 512
static constexpr int OFF_PART = OFF_MASK + 512;       // 512
static constexpr int OFF_POOL = OFF_PART + 512;       // 64
static constexpr int OFF_QH   = OFF_POOL + 64;
static constexpr int OFF_OF   = OFF_QH + 64;
static constexpr int OFF_BG   = OFF_OF + 64;
static constexpr int OFF_BO   = OFF_BG + 64;
static constexpr int OFF_MS   = OFF_BO + 64;
static constexpr int SMEM_FLOATS = OFF_MS + 4;        // 54596
static constexpr int SMEM_BYTES  = SMEM_FLOATS * 4;   // ~218 KB

__device__ __forceinline__ uint32_t f2tf32(float x) {
    uint32_t u; asm("cvt.rna.tf32.f32 %0, %1;" : "=r"(u) : "f"(x)); return u;
}

__device__ __forceinline__ void mma_tf32(float c[4],
    uint32_t a0, uint32_t a1, uint32_t a2, uint32_t a3,
    uint32_t b0, uint32_t b1)
{
    asm("mma.sync.aligned.m16n8k8.row.col.f32.tf32.tf32.f32 "
        "{%0,%1,%2,%3}, {%4,%5,%6,%7}, {%8,%9}, {%0,%1,%2,%3};"
        : "+f"(c[0]), "+f"(c[1]), "+f"(c[2]), "+f"(c[3])
        : "r"(a0), "r"(a1), "r"(a2), "r"(a3), "r"(b0), "r"(b1));
}

__global__ void __launch_bounds__(NT, 1) ga_kernel(
    const float* __restrict__ m, const float* __restrict__ mask,
    const float* __restrict__ Wq, const float* __restrict__ Wk,
    const float* __restrict__ Wv, const float* __restrict__ Wg,
    const float* __restrict__ bg, const float* __restrict__ Wo,
    const float* __restrict__ bo, float* __restrict__ out)
{
    extern __shared__ float sm[];
    const int s    = blockIdx.x;
    const int tid  = threadIdx.x;
    const int warp = tid >> 5, lane = tid & 31;
    const int qrow = lane >> 2, qcol = lane & 3;   // mma quad coords
    const float* m_s = m + (size_t)s * (RR * 64);

    // ---------- Phase 0: stage m (stride 68) + weights in mma-fragment order ----------
    {
        const float4* m4 = (const float4*)m_s;
        #pragma unroll
        for (int i = tid; i < RR * 64 / 4; i += NT) {
            float4 v = m4[i];
            int r = i >> 4;
            int c = (i & 15) << 2;
            *(float4*)&sm[OFF_M + r * MSTR + c] = v;
        }
        // B-fragment layout for m16n8k8.row.col: b0 = W[kt*8 + lane%4][nt*8 + lane/4],
        // b1 = W[kt*8 + lane%4 + 4][same col]; stored as tf32 bits, 2 words per lane.
        uint32_t* smu = (uint32_t*)sm;
        int grp = tid >> 5;   // 16 groups of 32 lanes
        #pragma unroll
        for (int it = 0; it < 4; ++it) {
            int idx = it * 16 + grp;       // 0..63 -> (nt, kt)
            int nt = idx >> 3, kt = idx & 7;
            int dr = kt * 8 + qcol;
            int cc = nt * 8 + qrow;
            int off = ((nt * 8 + kt) * 32 + lane) * 2;
            smu[OFF_WGF + off]     = f2tf32(Wg[dr * 64 + cc]);
            smu[OFF_WGF + off + 1] = f2tf32(Wg[(dr + 4) * 64 + cc]);
            smu[OFF_WOF + off]     = f2tf32(Wo[dr * 64 + cc]);
            smu[OFF_WOF + off + 1] = f2tf32(Wo[(dr + 4) * 64 + cc]);
        }
        if (grp < 8) {
            int kt = grp;
            int dr = kt * 8 + qcol;
            int cc = qrow;
            int off = (kt * 32 + lane) * 2;
            smu[OFF_WKF + off]     = f2tf32(Wk[dr * 8 + cc]);
            smu[OFF_WKF + off + 1] = f2tf32(Wk[(dr + 4) * 8 + cc]);
            smu[OFF_WVF + off]     = f2tf32(Wv[dr * 8 + cc]);
            smu[OFF_WVF + off + 1] = f2tf32(Wv[(dr + 4) * 8 + cc]);
        }
        sm[OFF_MASK + tid] = mask[(size_t)s * RR + tid];
        if (tid < 64) { sm[OFF_BG + tid] = bg[tid]; sm[OFF_BO + tid] = bo[tid]; }
    }
    __syncthreads();

    // ---------- Phase 1: masked mean-pool ----------
    {
        int part = tid >> 6, d = tid & 63;
        float acc = 0.f;
        #pragma unroll 8
        for (int j = 0; j < 64; ++j) {
            int r = part * 64 + j;
            acc += sm[OFF_M + r * MSTR + d] * sm[OFF_MASK + r];
        }
        sm[OFF_PART + part * 64 + d] = acc;
    }
    if (tid < 32) {
        float ms = 0.f;
        #pragma unroll
        for (int j = 0; j < 16; ++j) ms += sm[OFF_MASK + tid + 32 * j];
        #pragma unroll
        for (int o = 16; o; o >>= 1) ms += __shfl_xor_sync(0xFFFFFFFFu, ms, o);
        if (tid == 0) sm[OFF_MS] = ms;
    }
    __syncthreads();
    if (tid < 64) {
        float p = 0.f;
        #pragma unroll
        for (int part = 0; part < 8; ++part) p += sm[OFF_PART + part * 64 + tid];
        sm[OFF_POOL + tid] = p / (sm[OFF_MS] + 1e-10f);
    }
    __syncthreads();

    // ---------- Phase 2: q = (pool @ Wq) * hd^-0.5 ----------
    if (tid < 64) {
        float acc = 0.f;
        #pragma unroll 8
        for (int d = 0; d < 64; ++d) acc += sm[OFF_POOL + d] * Wq[d * 64 + tid];
        sm[OFF_QH + tid] = acc * 0.35355339059327373f;
    }
    __syncthreads();

    // ================= tensor-core section: each warp owns rows r0..r0+31 =================
    const int r0 = warp * 32;

    // A fragments of m: Af[mt][kt][{a0,a1,a2,a3}] (conflict-free: banks 4*qrow+qcol)
    uint32_t Af[2][8][4];
    #pragma unroll
    for (int mt = 0; mt < 2; ++mt)
        #pragma unroll
        for (int kt = 0; kt < 8; ++kt) {
            int row = r0 + mt * 16 + qrow;
            int col = kt * 8 + qcol;
            Af[mt][kt][0] = f2tf32(sm[OFF_M + row * MSTR + col]);
            Af[mt][kt][1] = f2tf32(sm[OFF_M + (row + 8) * MSTR + col]);
            Af[mt][kt][2] = f2tf32(sm[OFF_M + row * MSTR + col + 4]);
            Af[mt][kt][3] = f2tf32(sm[OFF_M + (row + 8) * MSTR + col + 4]);
        }

    // ---------- Phase 3: k = m@Wk, v = m@Wv via mma ----------
    {
        const uint32_t* smu = (const uint32_t*)sm;
        float ck[2][4] = {{0,0,0,0},{0,0,0,0}};
        float cv[2][4] = {{0,0,0,0},{0,0,0,0}};
        #pragma unroll
        for (int kt = 0; kt < 8; ++kt) {
            uint32_t bk0 = smu[OFF_WKF + (kt * 32 + lane) * 2];
            uint32_t bk1 = smu[OFF_WKF + (kt * 32 + lane) * 2 + 1];
            uint32_t bv0 = smu[OFF_WVF + (kt * 32 + lane) * 2];
            uint32_t bv1 = smu[OFF_WVF + (kt * 32 + lane) * 2 + 1];
            #pragma unroll
            for (int mt = 0; mt < 2; ++mt) {
                mma_tf32(ck[mt], Af[mt][kt][0], Af[mt][kt][1], Af[mt][kt][2], Af[mt][kt][3], bk0, bk1);
                mma_tf32(cv[mt], Af[mt][kt][0], Af[mt][kt][1], Af[mt][kt][2], Af[mt][kt][3], bv0, bv1);
            }
        }
        #pragma unroll
        for (int mt = 0; mt < 2; ++mt) {
            int row = r0 + mt * 16 + qrow;
            int col = qcol * 2;
            sm[OFF_K + row * KSTR + col]           = ck[mt][0];
            sm[OFF_K + row * KSTR + col + 1]       = ck[mt][1];
            sm[OFF_K + (row + 8) * KSTR + col]     = ck[mt][2];
            sm[OFF_K + (row + 8) * KSTR + col + 1] = ck[mt][3];
            sm[OFF_V + row * KSTR + col]           = cv[mt][0];
            sm[OFF_V + row * KSTR + col + 1]       = cv[mt][1];
            sm[OFF_V + (row + 8) * KSTR + col]     = cv[mt][2];
            sm[OFF_V + (row + 8) * KSTR + col + 1] = cv[mt][3];
        }
    }
    __syncthreads();

    // ---------- Phase 4: per-head attention (warp h = head h) ----------
    if (warp < 8) {
        const int h = warp;
        float qv[8];
        #pragma unroll
        for (int c = 0; c < 8; ++c) qv[c] = sm[OFF_QH + h * 8 + c];

        float sc[16];
        float mx = -1e30f;
        #pragma unroll
        for (int i = 0; i < 16; ++i) {
            int r = i * 32 + lane;
            const float* kr = &sm[OFF_K + r * KSTR];
            float a = qv[0]*kr[0] + qv[1]*kr[1] + qv[2]*kr[2] + qv[3]*kr[3]
                    + qv[4]*kr[4] + qv[5]*kr[5] + qv[6]*kr[6] + qv[7]*kr[7];
            a += 1e9f * (sm[OFF_MASK + r] - 1.0f);
            sc[i] = a;
            mx = fmaxf(mx, a);
        }
        #pragma unroll
        for (int o = 16; o; o >>= 1) mx = fmaxf(mx, __shfl_xor_sync(0xFFFFFFFFu, mx, o));

        float sum = 0.f;
        float oa[8] = {0,0,0,0,0,0,0,0};
        #pragma unroll
        for (int i = 0; i < 16; ++i) {
            int r = i * 32 + lane;
            float p = __expf(sc[i] - mx);
            sum += p;
            const float* vr = &sm[OFF_V + r * KSTR];
            #pragma unroll
            for (int c = 0; c < 8; ++c) oa[c] += p * vr[c];
        }
        #pragma unroll
        for (int o = 16; o; o >>= 1) sum += __shfl_xor_sync(0xFFFFFFFFu, sum, o);
        #pragma unroll
        for (int c = 0; c < 8; ++c) {
            #pragma unroll
            for (int o = 16; o; o >>= 1) oa[c] += __shfl_xor_sync(0xFFFFFFFFu, oa[c], o);
        }
        if (lane == 0) {
            float inv = 1.f / sum;
            #pragma unroll
            for (int c = 0; c < 8; ++c) sm[OFF_OF + h * 8 + c] = oa[c] * inv;
        }
    }
    __syncthreads();

    // ---------- Phase 5a: gate GEMM + sigmoid epilogue; h overwrites m (warp-local rows) ----------
    {
        const uint32_t* smu = (const uint32_t*)sm;
        #pragma unroll
        for (int nt = 0; nt < 8; ++nt) {
            float cg[2][4] = {{0,0,0,0},{0,0,0,0}};
            #pragma unroll
            for (int kt = 0; kt < 8; ++kt) {
                uint32_t b0 = smu[OFF_WGF + ((nt * 8 + kt) * 32 + lane) * 2];
                uint32_t b1 = smu[OFF_WGF + ((nt * 8 + kt) * 32 + lane) * 2 + 1];
                #pragma unroll
                for (int mt = 0; mt < 2; ++mt)
                    mma_tf32(cg[mt], Af[mt][kt][0], Af[mt][kt][1], Af[mt][kt][2], Af[mt][kt][3], b0, b1);
            }
            int col0 = nt * 8 + qcol * 2;
            float of0 = sm[OFF_OF + col0], of1 = sm[OFF_OF + col0 + 1];
            float bg0 = sm[OFF_BG + col0], bg1 = sm[OFF_BG + col0 + 1];
            #pragma unroll
            for (int mt = 0; mt < 2; ++mt) {
                int row = r0 + mt * 16 + qrow;
                float h0 = of0 / (1.f + __expf(-(cg[mt][0] + bg0)));
                float h1 = of1 / (1.f + __expf(-(cg[mt][1] + bg1)));
                float h2 = of0 / (1.f + __expf(-(cg[mt][2] + bg0)));
                float h3 = of1 / (1.f + __expf(-(cg[mt][3] + bg1)));
                *(float2*)&sm[OFF_M + row * MSTR + col0]       = make_float2(h0, h1);
                *(float2*)&sm[OFF_M + (row + 8) * MSTR + col0] = make_float2(h2, h3);
            }
        }
    }
    __syncwarp();

    // ---------- Phase 5b: re-fragment h, output GEMM, store ----------
    {
        #pragma unroll
        for (int mt = 0; mt < 2; ++mt)
            #pragma unroll
            for (int kt = 0; kt < 8; ++kt) {
                int row = r0 + mt * 16 + qrow;
                int col = kt * 8 + qcol;
                Af[mt][kt][0] = f2tf32(sm[OFF_M + row * MSTR + col]);
                Af[mt][kt][1] = f2tf32(sm[OFF_M + (row + 8) * MSTR + col]);
                Af[mt][kt][2] = f2tf32(sm[OFF_M + row * MSTR + col + 4]);
                Af[mt][kt][3] = f2tf32(sm[OFF_M + (row + 8) * MSTR + col + 4]);
            }
        const uint32_t* smu = (const uint32_t*)sm;
        float* outs = out + (size_t)s * (RR * 64);
        #pragma unroll
        for (int nt = 0; nt < 8; ++nt) {
            float co[2][4] = {{0,0,0,0},{0,0,0,0}};
            #pragma unroll
            for (int kt = 0; kt < 8; ++kt) {
                uint32_t b0 = smu[OFF_WOF + ((nt * 8 + kt) * 32 + lane) * 2];
                uint32_t b1 = smu[OFF_WOF + ((nt * 8 + kt) * 32 + lane) * 2 + 1];
                #pragma unroll
                for (int mt = 0; mt < 2; ++mt)
                    mma_tf32(co[mt], Af[mt][kt][0], Af[mt][kt][1], Af[mt][kt][2], Af[mt][kt][3], b0, b1);
            }
            int col0 = nt * 8 + qcol * 2;
            float bo0 = sm[OFF_BO + col0], bo1 = sm[OFF_BO + col0 + 1];
            #pragma unroll
            for (int mt = 0; mt < 2; ++mt) {
                int row = r0 + mt * 16 + qrow;
                *(float2*)&outs[row * 64 + col0]       = make_float2(co[mt][0] + bo0, co[mt][1] + bo1);
                *(float2*)&outs[(row + 8) * 64 + col0] = make_float2(co[mt][2] + bo0, co[mt][3] + bo1);
            }
        }
    }
}

extern "C" void kernel_launch(void* const* d_in, const int* in_sizes, int n_in,
                              void* d_out, int out_size) {
    (void)in_sizes; (void)n_in; (void)out_size;
    const float* m    = (const float*)d_in[0];
    const float* mask = (const float*)d_in[1];
    const float* Wq   = (const float*)d_in[2];
    const float* Wk   = (const float*)d_in[3];
    const float* Wv   = (const float*)d_in[4];
    const float* Wg   = (const float*)d_in[5];
    const float* bg   = (const float*)d_in[6];
    const float* Wo   = (const float*)d_in[7];
    const float* bo   = (const float*)d_in[8];
    float* out = (float*)d_out;

    cudaFuncSetAttribute(ga_kernel, cudaFuncAttributeMaxDynamicSharedMemorySize, SMEM_BYTES);
    ga_kernel<<<SS, NT, SMEM_BYTES>>>(m, mask, Wq, Wk, Wv, Wg, bg, Wo, bo, out);
}

// round 4
// speedup vs baseline: 5.2052x; 1.3232x over previous
#include <cuda_runtime.h>
#include <cuda_fp16.h>
#include <math.h>
#include <stdint.h>

#define SS 2048
#define RR 512
#define NT 512
#define MHW 36    // m row stride in 32-bit words (72 halves); 36 % 32 == 4 -> frag gather conflict-free
#define KSTR 9

// ---- shared memory layout (32-bit word offsets) ----
static constexpr int OFF_M    = 0;                    // fp16 m/h: 512*36 = 18432 words
static constexpr int OFF_WGF  = 18432;                // Wg fp16 B-frags: 8nt*4ktg*32*2 = 2048
static constexpr int OFF_WOF  = OFF_WGF + 2048;       // Wo frags 2048
static constexpr int OFF_WKF  = OFF_WOF + 2048;       // Wk frags 256
static constexpr int OFF_WVF  = OFF_WKF + 256;        // Wv frags 256
static constexpr int OFF_K    = OFF_WVF + 256;        // fp32 512*9
static constexpr int OFF_V    = OFF_K + RR * KSTR;
static constexpr int OFF_MASK = OFF_V + RR * KSTR;    // 512
static constexpr int OFF_PART = OFF_MASK + 512;       // 32*64 pool partials
static constexpr int OFF_POOL = OFF_PART + 2048;      // 64
static constexpr int OFF_QH   = OFF_POOL + 64;
static constexpr int OFF_OF   = OFF_QH + 64;
static constexpr int OFF_BG   = OFF_OF + 64;
static constexpr int OFF_BO   = OFF_BG + 64;
static constexpr int OFF_MS   = OFF_BO + 64;
static constexpr int SMEM_WORDS = OFF_MS + 4;         // 35140
static constexpr int SMEM_BYTES = SMEM_WORDS * 4;     // ~137 KB

__device__ __forceinline__ uint32_t packh2(float lo, float hi) {
    __half2 h = __floats2half2_rn(lo, hi);
    return *(uint32_t*)&h;
}

__device__ __forceinline__ void mma_f16(float c[4], const uint32_t a[4],
                                        uint32_t b0, uint32_t b1)
{
    asm("mma.sync.aligned.m16n8k16.row.col.f32.f16.f16.f32 "
        "{%0,%1,%2,%3}, {%4,%5,%6,%7}, {%8,%9}, {%0,%1,%2,%3};"
        : "+f"(c[0]), "+f"(c[1]), "+f"(c[2]), "+f"(c[3])
        : "r"(a[0]), "r"(a[1]), "r"(a[2]), "r"(a[3]), "r"(b0), "r"(b1));
}

__global__ void __launch_bounds__(NT, 1) ga_kernel(
    const float* __restrict__ m, const float* __restrict__ mask,
    const float* __restrict__ Wq, const float* __restrict__ Wk,
    const float* __restrict__ Wv, const float* __restrict__ Wg,
    const float* __restrict__ bg, const float* __restrict__ Wo,
    const float* __restrict__ bo, float* __restrict__ out)
{
    extern __shared__ float sm[];
    uint32_t* smu = (uint32_t*)sm;
    const int s    = blockIdx.x;
    const int tid  = threadIdx.x;
    const int warp = tid >> 5, lane = tid & 31;
    const int qrow = lane >> 2, qcol = lane & 3;
    const float* m_s    = m + (size_t)s * (RR * 64);
    const float* mask_g = mask + (size_t)s * RR;

    // ---------- Phase 0: stage m as fp16 + fold in masked pool partials + weight frags ----------
    {
        const float4* m4 = (const float4*)m_s;
        const int cg4 = tid & 15, rbase = tid >> 4;
        float px = 0.f, py = 0.f, pz = 0.f, pw = 0.f;
        #pragma unroll
        for (int j = 0; j < 16; ++j) {
            int r = rbase + j * 32;
            float4 v = m4[r * 16 + cg4];
            float mk = __ldg(mask_g + r);
            px += v.x * mk; py += v.y * mk; pz += v.z * mk; pw += v.w * mk;
            smu[OFF_M + r * MHW + cg4 * 2]     = packh2(v.x, v.y);
            smu[OFF_M + r * MHW + cg4 * 2 + 1] = packh2(v.z, v.w);
        }
        float4 pp; pp.x = px; pp.y = py; pp.z = pz; pp.w = pw;
        *(float4*)&sm[OFF_PART + rbase * 64 + cg4 * 4] = pp;
        sm[OFF_MASK + tid] = mask_g[tid];
        if (warp == 0) {
            float ms = 0.f;
            #pragma unroll
            for (int j = 0; j < 16; ++j) ms += __ldg(mask_g + lane + 32 * j);
            #pragma unroll
            for (int o = 16; o; o >>= 1) ms += __shfl_xor_sync(0xFFFFFFFFu, ms, o);
            if (lane == 0) sm[OFF_MS] = ms;
        }
        if (tid < 64) { sm[OFF_BG + tid] = bg[tid]; sm[OFF_BO + tid] = bo[tid]; }

        // B-fragments (m16n8k16.row.col): b0 = {W[k0][n], W[k0+1][n]}, b1 = {W[k0+8][n], W[k0+9][n]}
        // with k0 = ktg*16 + 2*qcol, n = nt*8 + qrow.  Stored 2 words per lane.
        #pragma unroll
        for (int it = 0; it < 2; ++it) {
            int idx = it * 16 + warp;        // 0..31 -> (nt, ktg)
            int nt = idx >> 2, ktg = idx & 3;
            int d0 = ktg * 16 + 2 * qcol;
            int cc = nt * 8 + qrow;
            int off = ((nt * 4 + ktg) * 32 + lane) * 2;
            smu[OFF_WGF + off]     = packh2(Wg[d0 * 64 + cc],      Wg[(d0 + 1) * 64 + cc]);
            smu[OFF_WGF + off + 1] = packh2(Wg[(d0 + 8) * 64 + cc], Wg[(d0 + 9) * 64 + cc]);
            smu[OFF_WOF + off]     = packh2(Wo[d0 * 64 + cc],      Wo[(d0 + 1) * 64 + cc]);
            smu[OFF_WOF + off + 1] = packh2(Wo[(d0 + 8) * 64 + cc], Wo[(d0 + 9) * 64 + cc]);
        }
        if (warp < 4) {
            int ktg = warp;
            int d0 = ktg * 16 + 2 * qcol;
            int off = (ktg * 32 + lane) * 2;
            smu[OFF_WKF + off]     = packh2(Wk[d0 * 8 + qrow],      Wk[(d0 + 1) * 8 + qrow]);
            smu[OFF_WKF + off + 1] = packh2(Wk[(d0 + 8) * 8 + qrow], Wk[(d0 + 9) * 8 + qrow]);
            smu[OFF_WVF + off]     = packh2(Wv[d0 * 8 + qrow],      Wv[(d0 + 1) * 8 + qrow]);
            smu[OFF_WVF + off + 1] = packh2(Wv[(d0 + 8) * 8 + qrow], Wv[(d0 + 9) * 8 + qrow]);
        }
    }
    __syncthreads();

    // ================= each warp owns rows r0..r0+31 =================
    const int r0 = warp * 32;

    // A-fragments of m (fp16): Af[mt][ktg][4], conflict-free gather
    uint32_t Af[2][4][4];
    #pragma unroll
    for (int mt = 0; mt < 2; ++mt)
        #pragma unroll
        for (int ktg = 0; ktg < 4; ++ktg) {
            int w = OFF_M + (r0 + mt * 16 + qrow) * MHW + ktg * 8 + qcol;
            Af[mt][ktg][0] = smu[w];
            Af[mt][ktg][1] = smu[w + 8 * MHW];
            Af[mt][ktg][2] = smu[w + 4];
            Af[mt][ktg][3] = smu[w + 8 * MHW + 4];
        }

    // ---------- Phase 3: k = m@Wk, v = m@Wv via mma ----------
    {
        uint32_t bk[4][2], bv[4][2];
        #pragma unroll
        for (int ktg = 0; ktg < 4; ++ktg) {
            bk[ktg][0] = smu[OFF_WKF + (ktg * 32 + lane) * 2];
            bk[ktg][1] = smu[OFF_WKF + (ktg * 32 + lane) * 2 + 1];
            bv[ktg][0] = smu[OFF_WVF + (ktg * 32 + lane) * 2];
            bv[ktg][1] = smu[OFF_WVF + (ktg * 32 + lane) * 2 + 1];
        }
        float ck[2][4] = {{0,0,0,0},{0,0,0,0}};
        float cv[2][4] = {{0,0,0,0},{0,0,0,0}};
        #pragma unroll
        for (int ktg = 0; ktg < 4; ++ktg)
            #pragma unroll
            for (int mt = 0; mt < 2; ++mt) {
                mma_f16(ck[mt], Af[mt][ktg], bk[ktg][0], bk[ktg][1]);
                mma_f16(cv[mt], Af[mt][ktg], bv[ktg][0], bv[ktg][1]);
            }
        #pragma unroll
        for (int mt = 0; mt < 2; ++mt) {
            int row = r0 + mt * 16 + qrow;
            int col = qcol * 2;
            sm[OFF_K + row * KSTR + col]           = ck[mt][0];
            sm[OFF_K + row * KSTR + col + 1]       = ck[mt][1];
            sm[OFF_K + (row + 8) * KSTR + col]     = ck[mt][2];
            sm[OFF_K + (row + 8) * KSTR + col + 1] = ck[mt][3];
            sm[OFF_V + row * KSTR + col]           = cv[mt][0];
            sm[OFF_V + row * KSTR + col + 1]       = cv[mt][1];
            sm[OFF_V + (row + 8) * KSTR + col]     = cv[mt][2];
            sm[OFF_V + (row + 8) * KSTR + col + 1] = cv[mt][3];
        }
    }

    // pool reduce (PART + MS were written before the staging barrier)
    if (tid < 64) {
        float pp = 0.f;
        #pragma unroll
        for (int g = 0; g < 32; ++g) pp += sm[OFF_PART + g * 64 + tid];
        sm[OFF_POOL + tid] = pp / (sm[OFF_MS] + 1e-10f);
    }
    __syncthreads();

    // ---------- Phase 2: q = (pool @ Wq) * hd^-0.5 ----------
    if (tid < 64) {
        float acc = 0.f;
        #pragma unroll 8
        for (int d = 0; d < 64; ++d) acc += sm[OFF_POOL + d] * Wq[d * 64 + tid];
        sm[OFF_QH + tid] = acc * 0.35355339059327373f;
    }
    __syncthreads();

    // ---------- Phase 4: per-head attention (warp h = head h), fp32 ----------
    if (warp < 8) {
        const int h = warp;
        float qv[8];
        #pragma unroll
        for (int c = 0; c < 8; ++c) qv[c] = sm[OFF_QH + h * 8 + c];

        float sc[16];
        float mx = -1e30f;
        #pragma unroll
        for (int i = 0; i < 16; ++i) {
            int r = i * 32 + lane;
            const float* kr = &sm[OFF_K + r * KSTR];
            float a = qv[0]*kr[0] + qv[1]*kr[1] + qv[2]*kr[2] + qv[3]*kr[3]
                    + qv[4]*kr[4] + qv[5]*kr[5] + qv[6]*kr[6] + qv[7]*kr[7];
            a += 1e9f * (sm[OFF_MASK + r] - 1.0f);
            sc[i] = a;
            mx = fmaxf(mx, a);
        }
        #pragma unroll
        for (int o = 16; o; o >>= 1) mx = fmaxf(mx, __shfl_xor_sync(0xFFFFFFFFu, mx, o));

        float sum = 0.f;
        float oa[8] = {0,0,0,0,0,0,0,0};
        #pragma unroll
        for (int i = 0; i < 16; ++i) {
            int r = i * 32 + lane;
            float p = __expf(sc[i] - mx);
            sum += p;
            const float* vr = &sm[OFF_V + r * KSTR];
            #pragma unroll
            for (int c = 0; c < 8; ++c) oa[c] += p * vr[c];
        }
        #pragma unroll
        for (int o = 16; o; o >>= 1) sum += __shfl_xor_sync(0xFFFFFFFFu, sum, o);
        #pragma unroll
        for (int c = 0; c < 8; ++c) {
            #pragma unroll
            for (int o = 16; o; o >>= 1) oa[c] += __shfl_xor_sync(0xFFFFFFFFu, oa[c], o);
        }
        if (lane == 0) {
            float inv = 1.f / sum;
            #pragma unroll
            for (int c = 0; c < 8; ++c) sm[OFF_OF + h * 8 + c] = oa[c] * inv;
        }
    }
    __syncthreads();

    // ---------- Phase 5a: gate GEMM + sigmoid epilogue; h (fp16) overwrites m rows ----------
    {
        #pragma unroll
        for (int nt = 0; nt < 8; ++nt) {
            uint32_t b[4][2];
            #pragma unroll
            for (int ktg = 0; ktg < 4; ++ktg) {
                b[ktg][0] = smu[OFF_WGF + ((nt * 4 + ktg) * 32 + lane) * 2];
                b[ktg][1] = smu[OFF_WGF + ((nt * 4 + ktg) * 32 + lane) * 2 + 1];
            }
            float cg[2][4] = {{0,0,0,0},{0,0,0,0}};
            #pragma unroll
            for (int ktg = 0; ktg < 4; ++ktg)
                #pragma unroll
                for (int mt = 0; mt < 2; ++mt)
                    mma_f16(cg[mt], Af[mt][ktg], b[ktg][0], b[ktg][1]);

            int col0 = nt * 8 + qcol * 2;
            float of0 = sm[OFF_OF + col0], of1 = sm[OFF_OF + col0 + 1];
            float bg0 = sm[OFF_BG + col0], bg1 = sm[OFF_BG + col0 + 1];
            #pragma unroll
            for (int mt = 0; mt < 2; ++mt) {
                int row = r0 + mt * 16 + qrow;
                float h0 = of0 / (1.f + __expf(-(cg[mt][0] + bg0)));
                float h1 = of1 / (1.f + __expf(-(cg[mt][1] + bg1)));
                float h2 = of0 / (1.f + __expf(-(cg[mt][2] + bg0)));
                float h3 = of1 / (1.f + __expf(-(cg[mt][3] + bg1)));
                smu[OFF_M + row * MHW + nt * 4 + qcol]       = packh2(h0, h1);
                smu[OFF_M + (row + 8) * MHW + nt * 4 + qcol] = packh2(h2, h3);
            }
        }
    }
    __syncwarp();

    // ---------- Phase 5b: re-fragment h, output GEMM, store ----------
    {
        #pragma unroll
        for (int mt = 0; mt < 2; ++mt)
            #pragma unroll
            for (int ktg = 0; ktg < 4; ++ktg) {
                int w = OFF_M + (r0 + mt * 16 + qrow) * MHW + ktg * 8 + qcol;
                Af[mt][ktg][0] = smu[w];
                Af[mt][ktg][1] = smu[w + 8 * MHW];
                Af[mt][ktg][2] = smu[w + 4];
                Af[mt][ktg][3] = smu[w + 8 * MHW + 4];
            }
        float* outs = out + (size_t)s * (RR * 64);
        #pragma unroll
        for (int nt = 0; nt < 8; ++nt) {
            uint32_t b[4][2];
            #pragma unroll
            for (int ktg = 0; ktg < 4; ++ktg) {
                b[ktg][0] = smu[OFF_WOF + ((nt * 4 + ktg) * 32 + lane) * 2];
                b[ktg][1] = smu[OFF_WOF + ((nt * 4 + ktg) * 32 + lane) * 2 + 1];
            }
            float co[2][4] = {{0,0,0,0},{0,0,0,0}};
            #pragma unroll
            for (int ktg = 0; ktg < 4; ++ktg)
                #pragma unroll
                for (int mt = 0; mt < 2; ++mt)
                    mma_f16(co[mt], Af[mt][ktg], b[ktg][0], b[ktg][1]);

            int col0 = nt * 8 + qcol * 2;
            float bo0 = sm[OFF_BO + col0], bo1 = sm[OFF_BO + col0 + 1];
            #pragma unroll
            for (int mt = 0; mt < 2; ++mt) {
                int row = r0 + mt * 16 + qrow;
                *(float2*)&outs[row * 64 + col0]       = make_float2(co[mt][0] + bo0, co[mt][1] + bo1);
                *(float2*)&outs[(row + 8) * 64 + col0] = make_float2(co[mt][2] + bo0, co[mt][3] + bo1);
            }
        }
    }
}

extern "C" void kernel_launch(void* const* d_in, const int* in_sizes, int n_in,
                              void* d_out, int out_size) {
    (void)in_sizes; (void)n_in; (void)out_size;
    const float* m    = (const float*)d_in[0];
    const float* mask = (const float*)d_in[1];
    const float* Wq   = (const float*)d_in[2];
    const float* Wk   = (const float*)d_in[3];
    const float* Wv   = (const float*)d_in[4];
    const float* Wg   = (const float*)d_in[5];
    const float* bg   = (const float*)d_in[6];
    const float* Wo   = (const float*)d_in[7];
    const float* bo   = (const float*)d_in[8];
    float* out = (float*)d_out;

    cudaFuncSetAttribute(ga_kernel, cudaFuncAttributeMaxDynamicSharedMemorySize, SMEM_BYTES);
    ga_kernel<<<SS, NT, SMEM_BYTES>>>(m, mask, Wq, Wk, Wv, Wg, bg, Wo, bo, out);
}

// round 5
// speedup vs baseline: 5.7332x; 1.1014x over previous
#include <cuda_runtime.h>
#include <cuda_fp16.h>
#include <math.h>
#include <stdint.h>

#define SS 2048
#define RR 512
#define NT 256
#define MHW 36    // m row stride in words (72 halves); 36 % 32 == 4 -> frag gather conflict-free

// ---- shared memory layout (32-bit word offsets) ----
static constexpr int OFF_M    = 0;                    // fp16 m/h: 512*36 = 18432
static constexpr int OFF_WGF  = 18432;                // Wg B-frags 2048
static constexpr int OFF_WOF  = OFF_WGF + 2048;       // Wo frags 2048
static constexpr int OFF_WKF  = OFF_WOF + 2048;       // Wk frags 256
static constexpr int OFF_WVF  = OFF_WKF + 256;        // Wv frags 256
static constexpr int OFF_KV   = OFF_WVF + 256;        // 512 rows * 9 words: K(4xh2) V(4xh2) bias(f32)
static constexpr int OFF_PART = OFF_KV + RR * 9;      // 8 warps * 64 pool partials
static constexpr int OFF_POOL = OFF_PART + 512;       // 64
static constexpr int OFF_QH   = OFF_POOL + 64;
static constexpr int OFF_OF   = OFF_QH + 64;
static constexpr int OFF_BG   = OFF_OF + 64;
static constexpr int OFF_BO   = OFF_BG + 64;
static constexpr int OFF_MS   = OFF_BO + 64;
static constexpr int SMEM_WORDS = OFF_MS + 4;         // 28484
static constexpr int SMEM_BYTES = SMEM_WORDS * 4;     // 113936 B -> 2 CTAs/SM

__device__ __forceinline__ uint32_t packh2(float lo, float hi) {
    __half2 h = __floats2half2_rn(lo, hi);
    return *(uint32_t*)&h;
}
__device__ __forceinline__ float2 h2f2(uint32_t u) {
    return __half22float2(*(__half2*)&u);
}
__device__ __forceinline__ void mma_f16(float c[4], const uint32_t a[4],
                                        uint32_t b0, uint32_t b1)
{
    asm("mma.sync.aligned.m16n8k16.row.col.f32.f16.f16.f32 "
        "{%0,%1,%2,%3}, {%4,%5,%6,%7}, {%8,%9}, {%0,%1,%2,%3};"
        : "+f"(c[0]), "+f"(c[1]), "+f"(c[2]), "+f"(c[3])
        : "r"(a[0]), "r"(a[1]), "r"(a[2]), "r"(a[3]), "r"(b0), "r"(b1));
}

__global__ void __launch_bounds__(NT, 2) ga_kernel(
    const float* __restrict__ m, const float* __restrict__ mask,
    const float* __restrict__ Wq, const float* __restrict__ Wk,
    const float* __restrict__ Wv, const float* __restrict__ Wg,
    const float* __restrict__ bg, const float* __restrict__ Wo,
    const float* __restrict__ bo, float* __restrict__ out)
{
    extern __shared__ float sm[];
    uint32_t* smu = (uint32_t*)sm;
    const int s    = blockIdx.x;
    const int tid  = threadIdx.x;
    const int warp = tid >> 5, lane = tid & 31;
    const int qrow = lane >> 2, qcol = lane & 3;
    const float* m_s    = m + (size_t)s * (RR * 64);
    const float* mask_g = mask + (size_t)s * RR;

    // ---------- Phase 0: stage m as fp16 + pool partials + KV bias + weight frags ----------
    {
        const float4* m4 = (const float4*)m_s;
        const int cg4 = tid & 15, rbase = tid >> 4;
        float px = 0.f, py = 0.f, pz = 0.f, pw = 0.f;
        #pragma unroll
        for (int j = 0; j < 32; ++j) {
            int r = rbase + j * 16;
            float4 v = m4[r * 16 + cg4];
            float mk = __ldg(mask_g + r);
            px += v.x * mk; py += v.y * mk; pz += v.z * mk; pw += v.w * mk;
            smu[OFF_M + r * MHW + cg4 * 2]     = packh2(v.x, v.y);
            smu[OFF_M + r * MHW + cg4 * 2 + 1] = packh2(v.z, v.w);
        }
        // combine lane pairs (l, l+16) share cg4 -> 8 partial groups of 64
        px += __shfl_down_sync(0xFFFFFFFFu, px, 16);
        py += __shfl_down_sync(0xFFFFFFFFu, py, 16);
        pz += __shfl_down_sync(0xFFFFFFFFu, pz, 16);
        pw += __shfl_down_sync(0xFFFFFFFFu, pw, 16);
        if (lane < 16) {
            float4 pp; pp.x = px; pp.y = py; pp.z = pz; pp.w = pw;
            *(float4*)&sm[OFF_PART + warp * 64 + cg4 * 4] = pp;
        }
        // mask bias folded into KV word 8
        #pragma unroll
        for (int i = tid; i < RR; i += NT)
            sm[OFF_KV + i * 9 + 8] = 1e9f * (__ldg(mask_g + i) - 1.0f);
        if (warp == 0) {
            float ms = 0.f;
            #pragma unroll
            for (int j = 0; j < 16; ++j) ms += __ldg(mask_g + lane + 32 * j);
            #pragma unroll
            for (int o = 16; o; o >>= 1) ms += __shfl_xor_sync(0xFFFFFFFFu, ms, o);
            if (lane == 0) sm[OFF_MS] = ms;
        }
        if (tid < 64) { sm[OFF_BG + tid] = bg[tid]; sm[OFF_BO + tid] = bo[tid]; }

        // B-fragments (m16n8k16.row.col): b0={W[k0][n],W[k0+1][n]}, b1={W[k0+8][n],W[k0+9][n]},
        // k0 = ktg*16 + 2*qcol, n = nt*8 + qrow
        #pragma unroll
        for (int it = 0; it < 4; ++it) {
            int idx = it * 8 + warp;          // 0..31 -> (nt, ktg)
            int nt = idx >> 2, ktg = idx & 3;
            int d0 = ktg * 16 + 2 * qcol;
            int cc = nt * 8 + qrow;
            int off = ((nt * 4 + ktg) * 32 + lane) * 2;
            smu[OFF_WGF + off]     = packh2(Wg[d0 * 64 + cc],       Wg[(d0 + 1) * 64 + cc]);
            smu[OFF_WGF + off + 1] = packh2(Wg[(d0 + 8) * 64 + cc], Wg[(d0 + 9) * 64 + cc]);
            smu[OFF_WOF + off]     = packh2(Wo[d0 * 64 + cc],       Wo[(d0 + 1) * 64 + cc]);
            smu[OFF_WOF + off + 1] = packh2(Wo[(d0 + 8) * 64 + cc], Wo[(d0 + 9) * 64 + cc]);
        }
        if (warp < 4) {
            int ktg = warp;
            int d0 = ktg * 16 + 2 * qcol;
            int off = (ktg * 32 + lane) * 2;
            smu[OFF_WKF + off]     = packh2(Wk[d0 * 8 + qrow],       Wk[(d0 + 1) * 8 + qrow]);
            smu[OFF_WKF + off + 1] = packh2(Wk[(d0 + 8) * 8 + qrow], Wk[(d0 + 9) * 8 + qrow]);
            smu[OFF_WVF + off]     = packh2(Wv[d0 * 8 + qrow],       Wv[(d0 + 1) * 8 + qrow]);
            smu[OFF_WVF + off + 1] = packh2(Wv[(d0 + 8) * 8 + qrow], Wv[(d0 + 9) * 8 + qrow]);
        }
    }
    __syncthreads();

    // ================= each warp owns 64 rows r0..r0+63 =================
    const int r0 = warp * 64;

    // A-fragments of m (fp16): 4 m-tiles x 4 k-groups
    uint32_t Af[4][4][4];
    #pragma unroll
    for (int mt = 0; mt < 4; ++mt)
        #pragma unroll
        for (int ktg = 0; ktg < 4; ++ktg) {
            int w = OFF_M + (r0 + mt * 16 + qrow) * MHW + ktg * 8 + qcol;
            Af[mt][ktg][0] = smu[w];
            Af[mt][ktg][1] = smu[w + 8 * MHW];
            Af[mt][ktg][2] = smu[w + 4];
            Af[mt][ktg][3] = smu[w + 8 * MHW + 4];
        }

    // ---------- Phase 3: k = m@Wk (then v = m@Wv), store fp16 into KV rows ----------
    {
        uint32_t b[4][2];
        #pragma unroll
        for (int ktg = 0; ktg < 4; ++ktg) {
            b[ktg][0] = smu[OFF_WKF + (ktg * 32 + lane) * 2];
            b[ktg][1] = smu[OFF_WKF + (ktg * 32 + lane) * 2 + 1];
        }
        float ck[4][4] = {{0,0,0,0},{0,0,0,0},{0,0,0,0},{0,0,0,0}};
        #pragma unroll
        for (int ktg = 0; ktg < 4; ++ktg)
            #pragma unroll
            for (int mt = 0; mt < 4; ++mt)
                mma_f16(ck[mt], Af[mt][ktg], b[ktg][0], b[ktg][1]);
        #pragma unroll
        for (int mt = 0; mt < 4; ++mt) {
            int row = r0 + mt * 16 + qrow;
            smu[OFF_KV + row * 9 + qcol]       = packh2(ck[mt][0], ck[mt][1]);
            smu[OFF_KV + (row + 8) * 9 + qcol] = packh2(ck[mt][2], ck[mt][3]);
        }
        #pragma unroll
        for (int ktg = 0; ktg < 4; ++ktg) {
            b[ktg][0] = smu[OFF_WVF + (ktg * 32 + lane) * 2];
            b[ktg][1] = smu[OFF_WVF + (ktg * 32 + lane) * 2 + 1];
        }
        float cv[4][4] = {{0,0,0,0},{0,0,0,0},{0,0,0,0},{0,0,0,0}};
        #pragma unroll
        for (int ktg = 0; ktg < 4; ++ktg)
            #pragma unroll
            for (int mt = 0; mt < 4; ++mt)
                mma_f16(cv[mt], Af[mt][ktg], b[ktg][0], b[ktg][1]);
        #pragma unroll
        for (int mt = 0; mt < 4; ++mt) {
            int row = r0 + mt * 16 + qrow;
            smu[OFF_KV + row * 9 + 4 + qcol]       = packh2(cv[mt][0], cv[mt][1]);
            smu[OFF_KV + (row + 8) * 9 + 4 + qcol] = packh2(cv[mt][2], cv[mt][3]);
        }
    }

    // ---------- pool reduce + q projection (warp 0 only, overlaps other warps' mma) ----------
    if (warp == 0) {
        float p0 = 0.f, p1 = 0.f;
        #pragma unroll
        for (int w = 0; w < 8; ++w) {
            p0 += sm[OFF_PART + w * 64 + lane];
            p1 += sm[OFF_PART + w * 64 + lane + 32];
        }
        float inv = 1.f / (sm[OFF_MS] + 1e-10f);
        sm[OFF_POOL + lane]      = p0 * inv;
        sm[OFF_POOL + lane + 32] = p1 * inv;
        __syncwarp();
        float q0 = 0.f, q1 = 0.f;
        #pragma unroll 8
        for (int d = 0; d < 64; ++d) {
            float pd = sm[OFF_POOL + d];
            q0 += pd * __ldg(&Wq[d * 64 + lane]);
            q1 += pd * __ldg(&Wq[d * 64 + lane + 32]);
        }
        sm[OFF_QH + lane]      = q0 * 0.35355339059327373f;
        sm[OFF_QH + lane + 32] = q1 * 0.35355339059327373f;
    }
    __syncthreads();

    // ---------- Phase 4: attention, warp = head (no max pass; scores O(1), mask bias -1e9 -> exp=0) ----------
    {
        const int h = warp;
        float qv[8];
        #pragma unroll
        for (int c = 0; c < 8; ++c) qv[c] = sm[OFF_QH + h * 8 + c];

        float sum = 0.f;
        float oa[8] = {0,0,0,0,0,0,0,0};
        #pragma unroll
        for (int i = 0; i < 16; ++i) {
            int r = i * 32 + lane;
            const uint32_t* kv = smu + OFF_KV + r * 9;
            float2 k0 = h2f2(kv[0]), k1 = h2f2(kv[1]), k2 = h2f2(kv[2]), k3 = h2f2(kv[3]);
            float bias = sm[OFF_KV + r * 9 + 8];
            float a = qv[0]*k0.x + qv[1]*k0.y + qv[2]*k1.x + qv[3]*k1.y
                    + qv[4]*k2.x + qv[5]*k2.y + qv[6]*k3.x + qv[7]*k3.y + bias;
            float p = __expf(a);
            sum += p;
            float2 v0 = h2f2(kv[4]), v1 = h2f2(kv[5]), v2 = h2f2(kv[6]), v3 = h2f2(kv[7]);
            oa[0] += p * v0.x; oa[1] += p * v0.y; oa[2] += p * v1.x; oa[3] += p * v1.y;
            oa[4] += p * v2.x; oa[5] += p * v2.y; oa[6] += p * v3.x; oa[7] += p * v3.y;
        }
        #pragma unroll
        for (int o = 16; o; o >>= 1) sum += __shfl_xor_sync(0xFFFFFFFFu, sum, o);
        #pragma unroll
        for (int c = 0; c < 8; ++c) {
            #pragma unroll
            for (int o = 16; o; o >>= 1) oa[c] += __shfl_xor_sync(0xFFFFFFFFu, oa[c], o);
        }
        if (lane == 0) {
            float inv = 1.f / sum;
            #pragma unroll
            for (int c = 0; c < 8; ++c) sm[OFF_OF + h * 8 + c] = oa[c] * inv;
        }
    }
    __syncthreads();

    // ---------- Phase 5a: gate GEMM + sigmoid; h (fp16) overwrites m rows (warp-local) ----------
    {
        #pragma unroll
        for (int nt = 0; nt < 8; ++nt) {
            uint32_t b[4][2];
            #pragma unroll
            for (int ktg = 0; ktg < 4; ++ktg) {
                b[ktg][0] = smu[OFF_WGF + ((nt * 4 + ktg) * 32 + lane) * 2];
                b[ktg][1] = smu[OFF_WGF + ((nt * 4 + ktg) * 32 + lane) * 2 + 1];
            }
            float cg[4][4] = {{0,0,0,0},{0,0,0,0},{0,0,0,0},{0,0,0,0}};
            #pragma unroll
            for (int ktg = 0; ktg < 4; ++ktg)
                #pragma unroll
                for (int mt = 0; mt < 4; ++mt)
                    mma_f16(cg[mt], Af[mt][ktg], b[ktg][0], b[ktg][1]);

            int col0 = nt * 8 + qcol * 2;
            float of0 = sm[OFF_OF + col0], of1 = sm[OFF_OF + col0 + 1];
            float bg0 = sm[OFF_BG + col0], bg1 = sm[OFF_BG + col0 + 1];
            #pragma unroll
            for (int mt = 0; mt < 4; ++mt) {
                int row = r0 + mt * 16 + qrow;
                float h0 = of0 / (1.f + __expf(-(cg[mt][0] + bg0)));
                float h1 = of1 / (1.f + __expf(-(cg[mt][1] + bg1)));
                float h2 = of0 / (1.f + __expf(-(cg[mt][2] + bg0)));
                float h3 = of1 / (1.f + __expf(-(cg[mt][3] + bg1)));
                smu[OFF_M + row * MHW + nt * 4 + qcol]       = packh2(h0, h1);
                smu[OFF_M + (row + 8) * MHW + nt * 4 + qcol] = packh2(h2, h3);
            }
        }
    }
    __syncwarp();

    // ---------- Phase 5b: re-fragment h, output GEMM, store ----------
    {
        #pragma unroll
        for (int mt = 0; mt < 4; ++mt)
            #pragma unroll
            for (int ktg = 0; ktg < 4; ++ktg) {
                int w = OFF_M + (r0 + mt * 16 + qrow) * MHW + ktg * 8 + qcol;
                Af[mt][ktg][0] = smu[w];
                Af[mt][ktg][1] = smu[w + 8 * MHW];
                Af[mt][ktg][2] = smu[w + 4];
                Af[mt][ktg][3] = smu[w + 8 * MHW + 4];
            }
        float* outs = out + (size_t)s * (RR * 64);
        #pragma unroll
        for (int nt = 0; nt < 8; ++nt) {
            uint32_t b[4][2];
            #pragma unroll
            for (int ktg = 0; ktg < 4; ++ktg) {
                b[ktg][0] = smu[OFF_WOF + ((nt * 4 + ktg) * 32 + lane) * 2];
                b[ktg][1] = smu[OFF_WOF + ((nt * 4 + ktg) * 32 + lane) * 2 + 1];
            }
            float co[4][4] = {{0,0,0,0},{0,0,0,0},{0,0,0,0},{0,0,0,0}};
            #pragma unroll
            for (int ktg = 0; ktg < 4; ++ktg)
                #pragma unroll
                for (int mt = 0; mt < 4; ++mt)
                    mma_f16(co[mt], Af[mt][ktg], b[ktg][0], b[ktg][1]);

            int col0 = nt * 8 + qcol * 2;
            float bo0 = sm[OFF_BO + col0], bo1 = sm[OFF_BO + col0 + 1];
            #pragma unroll
            for (int mt = 0; mt < 4; ++mt) {
                int row = r0 + mt * 16 + qrow;
                *(float2*)&outs[row * 64 + col0]       = make_float2(co[mt][0] + bo0, co[mt][1] + bo1);
                *(float2*)&outs[(row + 8) * 64 + col0] = make_float2(co[mt][2] + bo0, co[mt][3] + bo1);
            }
        }
    }
}

extern "C" void kernel_launch(void* const* d_in, const int* in_sizes, int n_in,
                              void* d_out, int out_size) {
    (void)in_sizes; (void)n_in; (void)out_size;
    const float* m    = (const float*)d_in[0];
    const float* mask = (const float*)d_in[1];
    const float* Wq   = (const float*)d_in[2];
    const float* Wk   = (const float*)d_in[3];
    const float* Wv   = (const float*)d_in[4];
    const float* Wg   = (const float*)d_in[5];
    const float* bg   = (const float*)d_in[6];
    const float* Wo   = (const float*)d_in[7];
    const float* bo   = (const float*)d_in[8];
    float* out = (float*)d_out;

    cudaFuncSetAttribute(ga_kernel, cudaFuncAttributeMaxDynamicSharedMemorySize, SMEM_BYTES);
    ga_kernel<<<SS, NT, SMEM_BYTES>>>(m, mask, Wq, Wk, Wv, Wg, bg, Wo, bo, out);
}